// round 8
// baseline (speedup 1.0000x reference)
#include <cuda_runtime.h>
#include <cuda_fp16.h>
#include <cstdint>

// Problem constants
#define NUM_B 16384
#define DIM_D 784
#define DIM_L 1024
#define KXP   832          // K of X padded to multiple of 64
#define NRP   1024         // recon N padded to multiple of 256
#define LAMBDA 0.3f
#define STEPSZ 0.1f

// ---------------- scratch (__device__ globals; no allocs allowed) ----------
__device__ float g_G [DIM_L * DIM_L];
__device__ float g_B [(size_t)NUM_B * DIM_L];
__device__ float g_U0[(size_t)NUM_B * DIM_L];
__device__ float g_U1[(size_t)NUM_B * DIM_L];
__device__ __half g_Aa[(size_t)NUM_B * DIM_L];
__device__ __half g_Ab[(size_t)NUM_B * DIM_L];
__device__ __half g_Ac[(size_t)NUM_B * DIM_L];        // a_lo for recon
__device__ __half g_Gh[DIM_L * DIM_L];
__device__ __half g_XPh[(size_t)NUM_B * KXP];
__device__ __half g_XPl[(size_t)NUM_B * KXP];
__device__ __half g_WT [DIM_L * KXP];                 // W^T fp16 [L, KXP]
__device__ __half g_WR [NRP * DIM_L];                 // W fp16 padded [NRP, L]

__device__ __forceinline__ float lca_thresh(float x) {
    return x > LAMBDA ? x - LAMBDA : 0.0f;
}

// ---------------- baseline-ISA tensor helpers ----------
__device__ __forceinline__ uint32_t smem_u32(const void* p) {
    uint32_t a;
    asm("{ .reg .u64 t; cvta.to.shared.u64 t, %1; cvt.u32.u64 %0, t; }"
        : "=r"(a) : "l"(p));
    return a;
}
__device__ __forceinline__ void cp16(uint32_t dst, const void* src) {
    asm volatile("cp.async.cg.shared.global [%0], [%1], 16;"
                 :: "r"(dst), "l"(src) : "memory");
}
__device__ __forceinline__ void cp_commit() {
    asm volatile("cp.async.commit_group;" ::: "memory");
}
template <int N>
__device__ __forceinline__ void cp_wait() {
    asm volatile("cp.async.wait_group %0;" :: "n"(N) : "memory");
}
__device__ __forceinline__ void ldsm_x4(uint32_t* r, uint32_t a) {
    asm volatile("ldmatrix.sync.aligned.m8n8.x4.shared.b16 {%0,%1,%2,%3}, [%4];"
                 : "=r"(r[0]), "=r"(r[1]), "=r"(r[2]), "=r"(r[3]) : "r"(a));
}
__device__ __forceinline__ void mma_f16(float* c, const uint32_t* a, const uint32_t* b) {
    asm volatile(
        "mma.sync.aligned.m16n8k16.row.col.f32.f16.f16.f32 "
        "{%0,%1,%2,%3}, {%4,%5,%6,%7}, {%8,%9}, {%0,%1,%2,%3};"
        : "+f"(c[0]), "+f"(c[1]), "+f"(c[2]), "+f"(c[3])
        : "r"(a[0]), "r"(a[1]), "r"(a[2]), "r"(a[3]), "r"(b[0]), "r"(b[1]));
}

// ============================================================================
// fp16 mma GEMM, CTA tile 128(M) x 256(N), 8 warps (2x4), warp tile 64x64,
// BK=64, 3-stage cp.async pipeline, occ 1.
// D = A0@B (+ A1@B if NPROD==2), fp32 accum. Epilogues:
//  EPI 0: step      u' = 0.9u + 0.1b - 0.1D; Uout fp32, Aout = fp16(thresh)
//  EPI 1: step-last same + Aout2 = lo half of fp16 split of thresh(u')
//  EPI 2: b         Cout = D fp32, Uout = 0.1D, Aout = fp16(thresh(0.1D))
//  EPI 3: recon     Cout = D fp32, col < DIM_D guard, ld = DIM_D
// ============================================================================
#define BK   64
#define PAD  72                         // fp16/row (144B pitch, conflict-free)
#define A_TB (128 * PAD * 2)            // 18432 B
#define B_TB (256 * PAD * 2)            // 36864 B

template<int NPROD, int EPI>
__global__ __launch_bounds__(256, 1)
void mma_gemm(const __half* __restrict__ A0p, const __half* __restrict__ A1p,
              const __half* __restrict__ Bmp,
              const float* __restrict__ Uin, const float* __restrict__ Bex,
              float* __restrict__ Uout,
              __half* __restrict__ Aout, __half* __restrict__ Aout2,
              float* __restrict__ Cout,
              int Kdim, int ldA, int ldB)
{
    constexpr int STAGE_B = NPROD * A_TB + B_TB;
    extern __shared__ __align__(16) char dsmem[];
    const uint32_t sb = smem_u32(dsmem);

    const int tid  = threadIdx.x;
    const int lane = tid & 31;
    const int wid  = tid >> 5;
    const int wy   = wid >> 2;    // 0..1 (M, 64 each)
    const int wx   = wid & 3;     // 0..3 (N, 64 each)
    const int m0   = blockIdx.y * 128;
    const int n0   = blockIdx.x * 256;
    const int NC   = Kdim >> 6;

    // A ldmatrix (x4 row-major 16x16)
    const int a_row = lane & 15;
    const int a_kh  = lane >> 4;
    uint32_t aoffs[4];
    #pragma unroll
    for (int mi = 0; mi < 4; mi++)
        aoffs[mi] = (uint32_t)((wy * 64 + mi * 16 + a_row) * PAD + a_kh * 8) * 2;

    // B ldmatrix (x4 covering an ni pair: n16 x k16)
    const int b_nr = ((lane >> 4) & 1) * 8 + (lane & 7);
    const int b_kh = (lane >> 3) & 1;
    uint32_t boffs[4];
    #pragma unroll
    for (int p = 0; p < 4; p++)
        boffs[p] = (uint32_t)((wx * 64 + p * 16 + b_nr) * PAD + b_kh * 8) * 2;

    // cp.async mapping
    const int c_row = tid >> 3;          // 0..31
    const int c_col = (tid & 7) * 8;     // fp16 col within 64

    float acc[4][8][4];
    #pragma unroll
    for (int i = 0; i < 4; i++)
        #pragma unroll
        for (int j = 0; j < 8; j++)
            #pragma unroll
            for (int q = 0; q < 4; q++) acc[i][j][q] = 0.0f;

    auto issue = [&](int c, int stage) {
        const int k0 = c * BK;
        const uint32_t base = sb + stage * STAGE_B;
        // A tiles: 128 rows
        #pragma unroll
        for (int t = 0; t < 4; t++) {
            const int row = c_row + t * 32;
            const uint32_t soff = (uint32_t)(row * PAD + c_col) * 2;
            cp16(base + soff, A0p + (size_t)(m0 + row) * ldA + k0 + c_col);
            if (NPROD == 2)
                cp16(base + A_TB + soff, A1p + (size_t)(m0 + row) * ldA + k0 + c_col);
        }
        // B tile: 256 rows
        #pragma unroll
        for (int t = 0; t < 8; t++) {
            const int row = c_row + t * 32;
            const uint32_t soff = (uint32_t)(row * PAD + c_col) * 2;
            cp16(base + NPROD * A_TB + soff,
                 Bmp + (size_t)(n0 + row) * ldB + k0 + c_col);
        }
        cp_commit();
    };

    issue(0, 0);
    if (NC > 1) issue(1, 1);

    #pragma unroll 1
    for (int c = 0; c < NC; c++) {
        if (c + 2 < NC) {
            issue(c + 2, (c + 2) % 3);
            cp_wait<2>();
        } else if (c + 1 < NC) {
            cp_wait<1>();
        } else {
            cp_wait<0>();
        }
        __syncthreads();

        const uint32_t base = sb + (c % 3) * STAGE_B;
        const uint32_t uB = base + NPROD * A_TB;

        #pragma unroll
        for (int kk = 0; kk < BK; kk += 16) {
            const uint32_t kb = (uint32_t)kk * 2;
            uint32_t af[4][4];
            uint32_t bq[4][4];
            #pragma unroll
            for (int p = 0; p < 4; p++)
                ldsm_x4(bq[p], uB + boffs[p] + kb);
            #pragma unroll
            for (int mi = 0; mi < 4; mi++)
                ldsm_x4(af[mi], base + aoffs[mi] + kb);
            #pragma unroll
            for (int mi = 0; mi < 4; mi++)
                #pragma unroll
                for (int ni = 0; ni < 8; ni++)
                    mma_f16(acc[mi][ni], af[mi], &bq[ni >> 1][(ni & 1) * 2]);
            if (NPROD == 2) {
                #pragma unroll
                for (int mi = 0; mi < 4; mi++)
                    ldsm_x4(af[mi], base + A_TB + aoffs[mi] + kb);
                #pragma unroll
                for (int mi = 0; mi < 4; mi++)
                    #pragma unroll
                    for (int ni = 0; ni < 8; ni++)
                        mma_f16(acc[mi][ni], af[mi], &bq[ni >> 1][(ni & 1) * 2]);
            }
        }
        __syncthreads();
    }

    // ---------------- epilogue ----------------
    const int g  = lane >> 2;
    const int tg = lane & 3;
    #pragma unroll
    for (int mi = 0; mi < 4; mi++) {
        #pragma unroll
        for (int ni = 0; ni < 8; ni++) {
            #pragma unroll
            for (int h = 0; h < 2; h++) {
                const int r = m0 + wy * 64 + mi * 16 + g + h * 8;
                const int c0 = n0 + wx * 64 + ni * 8 + tg * 2;
                const float d0 = acc[mi][ni][h * 2 + 0];
                const float d1 = acc[mi][ni][h * 2 + 1];
                if (EPI == 0 || EPI == 1) {
                    const size_t idx = (size_t)r * DIM_L + c0;
                    const float2 u2 = *(const float2*)(Uin + idx);
                    const float2 b2 = *(const float2*)(Bex + idx);
                    const float vx = (1.0f - STEPSZ) * u2.x + STEPSZ * b2.x - STEPSZ * d0;
                    const float vy = (1.0f - STEPSZ) * u2.y + STEPSZ * b2.y - STEPSZ * d1;
                    *(float2*)(Uout + idx) = make_float2(vx, vy);
                    const float a0 = lca_thresh(vx), a1 = lca_thresh(vy);
                    const __half h0 = __float2half_rn(a0);
                    const __half h1 = __float2half_rn(a1);
                    *(uint32_t*)(Aout + idx) =
                        ((uint32_t)__half_as_ushort(h1) << 16) | __half_as_ushort(h0);
                    if (EPI == 1) {
                        const __half l0 = __float2half_rn(a0 - __half2float(h0));
                        const __half l1 = __float2half_rn(a1 - __half2float(h1));
                        *(uint32_t*)(Aout2 + idx) =
                            ((uint32_t)__half_as_ushort(l1) << 16) | __half_as_ushort(l0);
                    }
                } else if (EPI == 2) {
                    const size_t idx = (size_t)r * DIM_L + c0;
                    *(float2*)(Cout + idx) = make_float2(d0, d1);
                    const float vx = STEPSZ * d0, vy = STEPSZ * d1;
                    *(float2*)(Uout + idx) = make_float2(vx, vy);
                    const __half h0 = __float2half_rn(lca_thresh(vx));
                    const __half h1 = __float2half_rn(lca_thresh(vy));
                    *(uint32_t*)(Aout + idx) =
                        ((uint32_t)__half_as_ushort(h1) << 16) | __half_as_ushort(h0);
                } else { // EPI == 3 (recon)
                    if (c0 < DIM_D)
                        *(float2*)(Cout + (size_t)r * DIM_D + c0) = make_float2(d0, d1);
                }
            }
        }
    }
}

// ============================================================================
// SIMT fp32 GEMM — g = W^T W - I only
// ============================================================================
__global__ __launch_bounds__(256, 2)
void gemm_g(const float* __restrict__ W, float* __restrict__ C)
{
    __shared__ float As[16][128];
    __shared__ float Bs[16][128];

    const int tid = threadIdx.x;
    const int m0 = blockIdx.y * 128;
    const int n0 = blockIdx.x * 128;
    const int tx4 = (tid & 15) * 4;
    const int ty4 = (tid >> 4) * 4;

    float acc[8][8];
    #pragma unroll
    for (int i = 0; i < 8; i++)
        #pragma unroll
        for (int j = 0; j < 8; j++) acc[i][j] = 0.0f;

    for (int k0 = 0; k0 < DIM_D; k0 += 16) {
        {
            const int k  = tid >> 4;
            const int mq = (tid & 15) * 8;
            const float* src = W + (size_t)(k0 + k) * DIM_L + m0 + mq;
            *(float4*)&As[k][mq]     = *(const float4*)(src);
            *(float4*)&As[k][mq + 4] = *(const float4*)(src + 4);
        }
        {
            const int k  = tid >> 4;
            const int nq = (tid & 15) * 8;
            const float* src = W + (size_t)(k0 + k) * DIM_L + n0 + nq;
            *(float4*)&Bs[k][nq]     = *(const float4*)(src);
            *(float4*)&Bs[k][nq + 4] = *(const float4*)(src + 4);
        }
        __syncthreads();
        #pragma unroll
        for (int kk = 0; kk < 16; kk++) {
            float4 a0 = *(const float4*)&As[kk][ty4];
            float4 a1 = *(const float4*)&As[kk][ty4 + 64];
            float4 b0 = *(const float4*)&Bs[kk][tx4];
            float4 b1 = *(const float4*)&Bs[kk][tx4 + 64];
            float ar[8] = {a0.x, a0.y, a0.z, a0.w, a1.x, a1.y, a1.z, a1.w};
            float br[8] = {b0.x, b0.y, b0.z, b0.w, b1.x, b1.y, b1.z, b1.w};
            #pragma unroll
            for (int i = 0; i < 8; i++)
                #pragma unroll
                for (int j = 0; j < 8; j++)
                    acc[i][j] += ar[i] * br[j];
        }
        __syncthreads();
    }

    #pragma unroll
    for (int ih = 0; ih < 2; ih++)
        #pragma unroll
        for (int ii = 0; ii < 4; ii++) {
            const int row = m0 + ih * 64 + ty4 + ii;
            #pragma unroll
            for (int jh = 0; jh < 2; jh++) {
                const int col = n0 + jh * 64 + tx4;
                const size_t idx = (size_t)row * DIM_L + col;
                float4 v;
                v.x = acc[ih * 4 + ii][jh * 4 + 0];
                v.y = acc[ih * 4 + ii][jh * 4 + 1];
                v.z = acc[ih * 4 + ii][jh * 4 + 2];
                v.w = acc[ih * 4 + ii][jh * 4 + 3];
                if (row == col + 0) v.x -= 1.0f;
                if (row == col + 1) v.y -= 1.0f;
                if (row == col + 2) v.z -= 1.0f;
                if (row == col + 3) v.w -= 1.0f;
                *(float4*)&C[idx] = v;
            }
        }
}

// ---------------- conversion kernels (one-time) ----------------
__global__ void cvt_g_kernel(const float* __restrict__ src, __half* __restrict__ dst)
{
    const size_t i = ((size_t)blockIdx.x * blockDim.x + threadIdx.x) * 4;
    const float4 v = *(const float4*)(src + i);
    uint32_t p[2];
    p[0] = ((uint32_t)__half_as_ushort(__float2half_rn(v.y)) << 16) |
           __half_as_ushort(__float2half_rn(v.x));
    p[1] = ((uint32_t)__half_as_ushort(__float2half_rn(v.w)) << 16) |
           __half_as_ushort(__float2half_rn(v.z));
    *(uint2*)(dst + i) = *(const uint2*)p;
}

__global__ void split_pad_x(const float* __restrict__ X,
                            __half* __restrict__ hi, __half* __restrict__ lo)
{
    const size_t v = (size_t)blockIdx.x * blockDim.x + threadIdx.x;
    const int row = (int)(v / (KXP / 4));
    const int c4  = (int)(v % (KXP / 4)) * 4;
    uint32_t hp[2] = {0, 0}, lp[2] = {0, 0};
    if (c4 < DIM_D) {
        const float4 x = *(const float4*)(X + (size_t)row * DIM_D + c4);
        const __half h0 = __float2half_rn(x.x), h1 = __float2half_rn(x.y);
        const __half h2 = __float2half_rn(x.z), h3 = __float2half_rn(x.w);
        const __half l0 = __float2half_rn(x.x - __half2float(h0));
        const __half l1 = __float2half_rn(x.y - __half2float(h1));
        const __half l2 = __float2half_rn(x.z - __half2float(h2));
        const __half l3 = __float2half_rn(x.w - __half2float(h3));
        hp[0] = ((uint32_t)__half_as_ushort(h1) << 16) | __half_as_ushort(h0);
        hp[1] = ((uint32_t)__half_as_ushort(h3) << 16) | __half_as_ushort(h2);
        lp[0] = ((uint32_t)__half_as_ushort(l1) << 16) | __half_as_ushort(l0);
        lp[1] = ((uint32_t)__half_as_ushort(l3) << 16) | __half_as_ushort(l2);
    }
    const size_t o = (size_t)row * KXP + c4;
    *(uint2*)(hi + o) = *(const uint2*)hp;
    *(uint2*)(lo + o) = *(const uint2*)lp;
}

__global__ void transpose_w(const float* __restrict__ W, __half* __restrict__ WT)
{
    const size_t i = (size_t)blockIdx.x * blockDim.x + threadIdx.x;
    if (i >= (size_t)DIM_L * KXP) return;
    const int n = (int)(i / KXP);
    const int k = (int)(i % KXP);
    const float v = (k < DIM_D) ? W[(size_t)k * DIM_L + n] : 0.0f;
    WT[i] = __float2half_rn(v);
}

__global__ void pad_w(const float* __restrict__ W, __half* __restrict__ WR)
{
    const size_t i = ((size_t)blockIdx.x * blockDim.x + threadIdx.x) * 4;
    if (i >= (size_t)NRP * DIM_L) return;
    const int row = (int)(i / DIM_L);
    uint32_t p[2] = {0, 0};
    if (row < DIM_D) {
        const float4 v = *(const float4*)(W + i);
        p[0] = ((uint32_t)__half_as_ushort(__float2half_rn(v.y)) << 16) |
               __half_as_ushort(__float2half_rn(v.x));
        p[1] = ((uint32_t)__half_as_ushort(__float2half_rn(v.w)) << 16) |
               __half_as_ushort(__float2half_rn(v.z));
    }
    *(uint2*)(WR + i) = *(const uint2*)p;
}

// ============================================================================
extern "C" void kernel_launch(void* const* d_in, const int* in_sizes, int n_in,
                              void* d_out, int out_size) {
    (void)n_in; (void)out_size;

    const float* x = (const float*)d_in[0];
    const float* w = (const float*)d_in[1];
    if (in_sizes[0] == DIM_D * DIM_L) {
        x = (const float*)d_in[1];
        w = (const float*)d_in[0];
    }
    float* out = (float*)d_out;

    float *G, *Bb, *U0, *U1;
    __half *Aa, *Ab, *Ac, *Gh, *XPh, *XPl, *WT, *WR;
    cudaGetSymbolAddress((void**)&G,   g_G);
    cudaGetSymbolAddress((void**)&Bb,  g_B);
    cudaGetSymbolAddress((void**)&U0,  g_U0);
    cudaGetSymbolAddress((void**)&U1,  g_U1);
    cudaGetSymbolAddress((void**)&Aa,  g_Aa);
    cudaGetSymbolAddress((void**)&Ab,  g_Ab);
    cudaGetSymbolAddress((void**)&Ac,  g_Ac);
    cudaGetSymbolAddress((void**)&Gh,  g_Gh);
    cudaGetSymbolAddress((void**)&XPh, g_XPh);
    cudaGetSymbolAddress((void**)&XPl, g_XPl);
    cudaGetSymbolAddress((void**)&WT,  g_WT);
    cudaGetSymbolAddress((void**)&WR,  g_WR);

    const int SM1 = 3 * (1 * A_TB + B_TB);   // 165888
    const int SM2 = 3 * (2 * A_TB + B_TB);   // 221184
    cudaFuncSetAttribute(mma_gemm<1, 0>, cudaFuncAttributeMaxDynamicSharedMemorySize, SM1);
    cudaFuncSetAttribute(mma_gemm<1, 1>, cudaFuncAttributeMaxDynamicSharedMemorySize, SM1);
    cudaFuncSetAttribute(mma_gemm<2, 2>, cudaFuncAttributeMaxDynamicSharedMemorySize, SM2);
    cudaFuncSetAttribute(mma_gemm<2, 3>, cudaFuncAttributeMaxDynamicSharedMemorySize, SM2);

    // g = W^T W - I (fp32 SIMT)
    gemm_g<<<dim3(8, 8), 256>>>(w, G);
    // conversions
    cvt_g_kernel<<<(DIM_L * DIM_L) / 4 / 256, 256>>>(G, Gh);
    split_pad_x<<<(int)(((size_t)NUM_B * KXP / 4) / 256), 256>>>(x, XPh, XPl);
    transpose_w<<<(DIM_L * KXP + 255) / 256, 256>>>(w, WT);
    pad_w<<<(NRP * DIM_L / 4 + 255) / 256, 256>>>(w, WR);

    // b = X@W (fp16 2-product) + fused u1 = 0.1b, a1 = fp16(thresh(u1))
    mma_gemm<2, 2><<<dim3(4, 128), 256, SM2>>>(
        XPh, XPl, WT, nullptr, nullptr, U0, Aa, nullptr, Bb, KXP, KXP, KXP);

    // steps 2..49: 47 normal + 1 split-output
    float* uin = U0;  float* uout = U1;
    __half *ain = Aa, *aout = Ab;
    for (int s = 0; s < 47; s++) {
        mma_gemm<1, 0><<<dim3(4, 128), 256, SM1>>>(
            ain, nullptr, Gh, uin, Bb, uout, aout, nullptr, nullptr,
            DIM_L, DIM_L, DIM_L);
        float* tu = uin; uin = uout; uout = tu;
        __half* ta = ain; ain = aout; aout = ta;
    }
    mma_gemm<1, 1><<<dim3(4, 128), 256, SM1>>>(
        ain, nullptr, Gh, uin, Bb, uout, aout, Ac, nullptr,
        DIM_L, DIM_L, DIM_L);

    // recon = a@W^T (fp16 2-product), N guard < 784
    mma_gemm<2, 3><<<dim3(4, 128), 256, SM2>>>(
        aout, Ac, WR, nullptr, nullptr, nullptr, nullptr, nullptr, out,
        DIM_L, DIM_L, DIM_L);
}

// round 11
// speedup vs baseline: 1.2386x; 1.2386x over previous
#include <cuda_runtime.h>
#include <cuda_fp16.h>
#include <cstdint>

// Problem constants
#define NUM_B 16384
#define DIM_D 784
#define DIM_L 1024
#define KXP   832          // K of X padded to multiple of 64
#define NRP   896          // recon N padded to multiple of 128
#define LAMBDA 0.3f
#define STEPSZ 0.1f

// ---------------- scratch (__device__ globals; no allocs allowed) ----------
__device__ float g_B [(size_t)NUM_B * DIM_L];         // fp32 b
__device__ float g_U0[(size_t)NUM_B * DIM_L];
__device__ float g_U1[(size_t)NUM_B * DIM_L];
__device__ __half g_Aa[(size_t)NUM_B * DIM_L];        // a ping
__device__ __half g_Ab[(size_t)NUM_B * DIM_L];        // a pong
__device__ __half g_Gh[DIM_L * DIM_L];                // fp16(G)
__device__ __half g_XPh[(size_t)NUM_B * KXP];         // X hi, K-padded
__device__ __half g_XPl[(size_t)NUM_B * KXP];         // X lo
__device__ __half g_WTh[DIM_L * KXP];                 // W^T hi fp16 [L, KXP]
__device__ __half g_WTl[DIM_L * KXP];                 // W^T lo fp16
__device__ __half g_WR [NRP * DIM_L];                 // W fp16 padded [NRP, L]

__device__ __forceinline__ float lca_thresh(float x) {
    return x > LAMBDA ? x - LAMBDA : 0.0f;
}

// ---------------- baseline-ISA tensor helpers ----------
__device__ __forceinline__ uint32_t smem_u32(const void* p) {
    uint32_t a;
    asm("{ .reg .u64 t; cvta.to.shared.u64 t, %1; cvt.u32.u64 %0, t; }"
        : "=r"(a) : "l"(p));
    return a;
}
__device__ __forceinline__ void cp16(uint32_t dst, const void* src) {
    asm volatile("cp.async.cg.shared.global [%0], [%1], 16;"
                 :: "r"(dst), "l"(src) : "memory");
}
__device__ __forceinline__ void cp_commit() {
    asm volatile("cp.async.commit_group;" ::: "memory");
}
template <int N>
__device__ __forceinline__ void cp_wait() {
    asm volatile("cp.async.wait_group %0;" :: "n"(N) : "memory");
}
__device__ __forceinline__ void ldsm_x4(uint32_t* r, uint32_t a) {
    asm volatile("ldmatrix.sync.aligned.m8n8.x4.shared.b16 {%0,%1,%2,%3}, [%4];"
                 : "=r"(r[0]), "=r"(r[1]), "=r"(r[2]), "=r"(r[3]) : "r"(a));
}
__device__ __forceinline__ void mma_f16(float* c, const uint32_t* a, const uint32_t* b) {
    asm volatile(
        "mma.sync.aligned.m16n8k16.row.col.f32.f16.f16.f32 "
        "{%0,%1,%2,%3}, {%4,%5,%6,%7}, {%8,%9}, {%0,%1,%2,%3};"
        : "+f"(c[0]), "+f"(c[1]), "+f"(c[2]), "+f"(c[3])
        : "r"(a[0]), "r"(a[1]), "r"(a[2]), "r"(a[3]), "r"(b[0]), "r"(b[1]));
}

// ============================================================================
// fp16 mma GEMM (R7 config): CTA tile 128x128, 8 warps (2x4), warp 64x32,
// BK=64, 2-stage cp.async pipeline, occ 2.
// D = A0@B (+ A1@B if NPROD==2), fp32 accum. Epilogues:
//  EPI 0: step   u' = 0.9u + 0.1b - 0.1D; Uout fp32, Aout = fp16(thresh)
//  EPI 2: b      Cout = D fp32, Uout = 0.1D, Aout = fp16(thresh(0.1D))
//  EPI 3: recon  Cout = D fp32, col < DIM_D guard, ld = DIM_D
//  EPI 4: G      Aout(=Gh) = fp16(D - I)
// ============================================================================
#define BK   64
#define PAD  72                        // fp16/row (144B pitch, conflict-free)
#define TILE_B (128 * PAD * 2)         // 18432 B

template<int NPROD, int EPI>
__global__ __launch_bounds__(256, 2)
void mma_gemm(const __half* __restrict__ A0p, const __half* __restrict__ A1p,
              const __half* __restrict__ Bmp,
              const float* __restrict__ Uin, const float* __restrict__ Bex,
              float* __restrict__ Uout,
              __half* __restrict__ Aout,
              float* __restrict__ Cout,
              int Kdim, int ldA, int ldB)
{
    constexpr int STAGE_B = (NPROD + 1) * TILE_B;
    extern __shared__ __align__(16) char dsmem[];
    const uint32_t sb = smem_u32(dsmem);

    const int tid  = threadIdx.x;
    const int lane = tid & 31;
    const int wid  = tid >> 5;
    const int wy   = wid >> 2;   // 0..1 (M)
    const int wx   = wid & 3;    // 0..3 (N)
    const int m0   = blockIdx.y * 128;
    const int n0   = blockIdx.x * 128;
    const int NC   = Kdim >> 6;

    // A ldmatrix (x4 row-major 16x16)
    const int a_row = lane & 15;
    const int a_kh  = lane >> 4;
    uint32_t aoffs[4];
    #pragma unroll
    for (int mi = 0; mi < 4; mi++)
        aoffs[mi] = (uint32_t)((wy * 64 + mi * 16 + a_row) * PAD + a_kh * 8) * 2;

    // B ldmatrix (x4 covering an ni pair: n16 x k16)
    const int b_nr = ((lane >> 4) & 1) * 8 + (lane & 7);
    const int b_kh = (lane >> 3) & 1;
    uint32_t boffs[2];
    #pragma unroll
    for (int p = 0; p < 2; p++)
        boffs[p] = (uint32_t)((wx * 32 + p * 16 + b_nr) * PAD + b_kh * 8) * 2;

    // cp.async mapping: per tile 128 rows x 64 fp16; 4x16B per thread
    const int c_row = tid >> 3;
    const int c_col = (tid & 7) * 8;

    float acc[4][4][4];
    #pragma unroll
    for (int i = 0; i < 4; i++)
        #pragma unroll
        for (int j = 0; j < 4; j++)
            #pragma unroll
            for (int q = 0; q < 4; q++) acc[i][j][q] = 0.0f;

    auto issue = [&](int c, int stage) {
        const int k0 = c * BK;
        const uint32_t base = sb + stage * STAGE_B;
        #pragma unroll
        for (int t = 0; t < 4; t++) {
            const int row = c_row + t * 32;
            const uint32_t soff = (uint32_t)(row * PAD + c_col) * 2;
            cp16(base + soff, A0p + (size_t)(m0 + row) * ldA + k0 + c_col);
            if (NPROD == 2)
                cp16(base + TILE_B + soff, A1p + (size_t)(m0 + row) * ldA + k0 + c_col);
            cp16(base + NPROD * TILE_B + soff,
                 Bmp + (size_t)(n0 + row) * ldB + k0 + c_col);
        }
        cp_commit();
    };

    issue(0, 0);

    #pragma unroll 1
    for (int c = 0; c < NC; c++) {
        if (c + 1 < NC) {
            issue(c + 1, (c + 1) & 1);
            cp_wait<1>();
        } else {
            cp_wait<0>();
        }
        __syncthreads();

        const uint32_t base = sb + (c & 1) * STAGE_B;
        const uint32_t uB = base + NPROD * TILE_B;

        #pragma unroll
        for (int kk = 0; kk < BK; kk += 16) {
            const uint32_t kb = (uint32_t)kk * 2;
            uint32_t af[4][4];
            uint32_t bq[2][4];
            #pragma unroll
            for (int p = 0; p < 2; p++)
                ldsm_x4(bq[p], uB + boffs[p] + kb);
            #pragma unroll
            for (int mi = 0; mi < 4; mi++)
                ldsm_x4(af[mi], base + aoffs[mi] + kb);
            #pragma unroll
            for (int mi = 0; mi < 4; mi++)
                #pragma unroll
                for (int ni = 0; ni < 4; ni++)
                    mma_f16(acc[mi][ni], af[mi], &bq[ni >> 1][(ni & 1) * 2]);
            if (NPROD == 2) {
                #pragma unroll
                for (int mi = 0; mi < 4; mi++)
                    ldsm_x4(af[mi], base + TILE_B + aoffs[mi] + kb);
                #pragma unroll
                for (int mi = 0; mi < 4; mi++)
                    #pragma unroll
                    for (int ni = 0; ni < 4; ni++)
                        mma_f16(acc[mi][ni], af[mi], &bq[ni >> 1][(ni & 1) * 2]);
            }
        }
        __syncthreads();
    }

    // ---------------- epilogue ----------------
    const int g  = lane >> 2;
    const int tg = lane & 3;
    #pragma unroll
    for (int mi = 0; mi < 4; mi++) {
        #pragma unroll
        for (int ni = 0; ni < 4; ni++) {
            #pragma unroll
            for (int h = 0; h < 2; h++) {
                const int r = m0 + wy * 64 + mi * 16 + g + h * 8;
                const int c0 = n0 + wx * 32 + ni * 8 + tg * 2;
                float d0 = acc[mi][ni][h * 2 + 0];
                float d1 = acc[mi][ni][h * 2 + 1];
                if (EPI == 0) {
                    const size_t idx = (size_t)r * DIM_L + c0;
                    const float2 u2 = *(const float2*)(Uin + idx);
                    const float2 b2 = *(const float2*)(Bex + idx);
                    const float vx = (1.0f - STEPSZ) * u2.x + STEPSZ * b2.x - STEPSZ * d0;
                    const float vy = (1.0f - STEPSZ) * u2.y + STEPSZ * b2.y - STEPSZ * d1;
                    *(float2*)(Uout + idx) = make_float2(vx, vy);
                    const __half h0 = __float2half_rn(lca_thresh(vx));
                    const __half h1 = __float2half_rn(lca_thresh(vy));
                    *(uint32_t*)(Aout + idx) =
                        ((uint32_t)__half_as_ushort(h1) << 16) | __half_as_ushort(h0);
                } else if (EPI == 2) {
                    const size_t idx = (size_t)r * DIM_L + c0;
                    *(float2*)(Cout + idx) = make_float2(d0, d1);
                    const float vx = STEPSZ * d0, vy = STEPSZ * d1;
                    *(float2*)(Uout + idx) = make_float2(vx, vy);
                    const __half h0 = __float2half_rn(lca_thresh(vx));
                    const __half h1 = __float2half_rn(lca_thresh(vy));
                    *(uint32_t*)(Aout + idx) =
                        ((uint32_t)__half_as_ushort(h1) << 16) | __half_as_ushort(h0);
                } else if (EPI == 3) { // recon
                    if (c0 < DIM_D)
                        *(float2*)(Cout + (size_t)r * DIM_D + c0) = make_float2(d0, d1);
                } else { // EPI == 4 : Gh = fp16(D - I)
                    if (r == c0 + 0) d0 -= 1.0f;
                    if (r == c0 + 1) d1 -= 1.0f;
                    const __half h0 = __float2half_rn(d0);
                    const __half h1 = __float2half_rn(d1);
                    *(uint32_t*)(Aout + (size_t)r * DIM_L + c0) =
                        ((uint32_t)__half_as_ushort(h1) << 16) | __half_as_ushort(h0);
                }
            }
        }
    }
}

// ---------------- conversion kernels (one-time) ----------------
// X [NUM_B,784] -> XPh/XPl [NUM_B,832] fp16 hi/lo, zero pad
__global__ void split_pad_x(const float* __restrict__ X,
                            __half* __restrict__ hi, __half* __restrict__ lo)
{
    const size_t v = (size_t)blockIdx.x * blockDim.x + threadIdx.x;
    const int row = (int)(v / (KXP / 4));
    const int c4  = (int)(v % (KXP / 4)) * 4;
    uint32_t hp[2] = {0, 0}, lp[2] = {0, 0};
    if (c4 < DIM_D) {
        const float4 x = *(const float4*)(X + (size_t)row * DIM_D + c4);
        const __half h0 = __float2half_rn(x.x), h1 = __float2half_rn(x.y);
        const __half h2 = __float2half_rn(x.z), h3 = __float2half_rn(x.w);
        const __half l0 = __float2half_rn(x.x - __half2float(h0));
        const __half l1 = __float2half_rn(x.y - __half2float(h1));
        const __half l2 = __float2half_rn(x.z - __half2float(h2));
        const __half l3 = __float2half_rn(x.w - __half2float(h3));
        hp[0] = ((uint32_t)__half_as_ushort(h1) << 16) | __half_as_ushort(h0);
        hp[1] = ((uint32_t)__half_as_ushort(h3) << 16) | __half_as_ushort(h2);
        lp[0] = ((uint32_t)__half_as_ushort(l1) << 16) | __half_as_ushort(l0);
        lp[1] = ((uint32_t)__half_as_ushort(l3) << 16) | __half_as_ushort(l2);
    }
    const size_t o = (size_t)row * KXP + c4;
    *(uint2*)(hi + o) = *(const uint2*)hp;
    *(uint2*)(lo + o) = *(const uint2*)lp;
}

// WTh/WTl [L, KXP] fp16 hi/lo : WT[n,k] = W[k,n] (k<784), else 0
__global__ void transpose_w(const float* __restrict__ W,
                            __half* __restrict__ WTh, __half* __restrict__ WTl)
{
    const size_t i = (size_t)blockIdx.x * blockDim.x + threadIdx.x;
    if (i >= (size_t)DIM_L * KXP) return;
    const int n = (int)(i / KXP);
    const int k = (int)(i % KXP);
    const float v = (k < DIM_D) ? W[(size_t)k * DIM_L + n] : 0.0f;
    const __half h = __float2half_rn(v);
    WTh[i] = h;
    WTl[i] = __float2half_rn(v - __half2float(h));
}

// WR [NRP, L] fp16 : rows < 784 = fp16(W), else 0
__global__ void pad_w(const float* __restrict__ W, __half* __restrict__ WR)
{
    const size_t i = ((size_t)blockIdx.x * blockDim.x + threadIdx.x) * 4;
    if (i >= (size_t)NRP * DIM_L) return;
    const int row = (int)(i / DIM_L);
    uint32_t p[2] = {0, 0};
    if (row < DIM_D) {
        const float4 v = *(const float4*)(W + i);
        p[0] = ((uint32_t)__half_as_ushort(__float2half_rn(v.y)) << 16) |
               __half_as_ushort(__float2half_rn(v.x));
        p[1] = ((uint32_t)__half_as_ushort(__float2half_rn(v.w)) << 16) |
               __half_as_ushort(__float2half_rn(v.z));
    }
    *(uint2*)(WR + i) = *(const uint2*)p;
}

// ============================================================================
extern "C" void kernel_launch(void* const* d_in, const int* in_sizes, int n_in,
                              void* d_out, int out_size) {
    (void)n_in; (void)out_size;

    const float* x = (const float*)d_in[0];
    const float* w = (const float*)d_in[1];
    if (in_sizes[0] == DIM_D * DIM_L) {
        x = (const float*)d_in[1];
        w = (const float*)d_in[0];
    }
    float* out = (float*)d_out;

    float *Bb, *U0, *U1;
    __half *Aa, *Ab, *Gh, *XPh, *XPl, *WTh, *WTl, *WR;
    cudaGetSymbolAddress((void**)&Bb,  g_B);
    cudaGetSymbolAddress((void**)&U0,  g_U0);
    cudaGetSymbolAddress((void**)&U1,  g_U1);
    cudaGetSymbolAddress((void**)&Aa,  g_Aa);
    cudaGetSymbolAddress((void**)&Ab,  g_Ab);
    cudaGetSymbolAddress((void**)&Gh,  g_Gh);
    cudaGetSymbolAddress((void**)&XPh, g_XPh);
    cudaGetSymbolAddress((void**)&XPl, g_XPl);
    cudaGetSymbolAddress((void**)&WTh, g_WTh);
    cudaGetSymbolAddress((void**)&WTl, g_WTl);
    cudaGetSymbolAddress((void**)&WR,  g_WR);

    const int SM1 = 2 * 2 * TILE_B;   // NPROD=1: 73728
    const int SM2 = 2 * 3 * TILE_B;   // NPROD=2: 110592
    cudaFuncSetAttribute(mma_gemm<1, 0>, cudaFuncAttributeMaxDynamicSharedMemorySize, SM1);
    cudaFuncSetAttribute(mma_gemm<1, 3>, cudaFuncAttributeMaxDynamicSharedMemorySize, SM1);
    cudaFuncSetAttribute(mma_gemm<2, 2>, cudaFuncAttributeMaxDynamicSharedMemorySize, SM2);
    cudaFuncSetAttribute(mma_gemm<2, 4>, cudaFuncAttributeMaxDynamicSharedMemorySize, SM2);

    // conversions
    transpose_w<<<(DIM_L * KXP + 255) / 256, 256>>>(w, WTh, WTl);
    split_pad_x<<<(int)(((size_t)NUM_B * KXP / 4) / 256), 256>>>(x, XPh, XPl);
    pad_w<<<(NRP * DIM_L / 4 + 255) / 256, 256>>>(w, WR);

    // Gh = fp16( (WTh+WTl) @ WTh - I )   (fp16 2-product, fused -I + cvt)
    mma_gemm<2, 4><<<dim3(8, 8), 256, SM2>>>(
        WTh, WTl, WTh, nullptr, nullptr, nullptr, Gh, nullptr, KXP, KXP, KXP);

    // b = X@W (fp16 2-product) + fused u1 = 0.1b, a1 = fp16(thresh(u1))
    mma_gemm<2, 2><<<dim3(8, 128), 256, SM2>>>(
        XPh, XPl, WTh, nullptr, nullptr, U0, Aa, Bb, KXP, KXP, KXP);

    // steps 2..49 (single-product fp16)
    float* uin = U0;  float* uout = U1;
    __half *ain = Aa, *aout = Ab;
    for (int s = 0; s < 48; s++) {
        mma_gemm<1, 0><<<dim3(8, 128), 256, SM1>>>(
            ain, nullptr, Gh, uin, Bb, uout, aout, nullptr, DIM_L, DIM_L, DIM_L);
        float* tu = uin; uin = uout; uout = tu;
        __half* ta = ain; ain = aout; aout = ta;
    }
    // After the final swap, the last-written activations are in `ain`.

    // recon = a_final@W^T (single-product fp16), N=784 guarded
    mma_gemm<1, 3><<<dim3(7, 128), 256, SM1>>>(
        ain, nullptr, WR, nullptr, nullptr, nullptr, nullptr, out,
        DIM_L, DIM_L, DIM_L);
}